// round 10
// baseline (speedup 1.0000x reference)
#include <cuda_runtime.h>

typedef unsigned long long u64;
#define TT 1024
#define NCTA 128

__device__ float    g_h[2][256][256];
__device__ unsigned g_bar;

__global__ void reset_kernel(){ if(threadIdx.x==0) g_bar=0u; }

__device__ __forceinline__ u64 dup2(float a){ u64 r; asm("mov.b64 %0,{%1,%1};":"=l"(r):"f"(a)); return r; }
__device__ __forceinline__ void fma2(u64& d, u64 a, u64 b){ asm("fma.rn.f32x2 %0,%1,%2,%0;":"+l"(d):"l"(a),"l"(b)); }
__device__ __forceinline__ float sigm(float x){ return 1.f/(1.f+__expf(-x)); }
__device__ __forceinline__ u64 bfly_add16(u64 v){
    unsigned lo,hi,lo2,hi2;
    asm("mov.b64 {%0,%1},%2;":"=r"(lo),"=r"(hi):"l"(v));
    asm("shfl.sync.bfly.b32 %0,%1,16,0x1f,0xffffffff;":"=r"(lo2):"r"(lo));
    asm("shfl.sync.bfly.b32 %0,%1,16,0x1f,0xffffffff;":"=r"(hi2):"r"(hi));
    u64 o,r;
    asm("mov.b64 %0,{%1,%2};":"=l"(o):"r"(lo2),"r"(hi2));
    asm("add.rn.f32x2 %0,%1,%2;":"=l"(r):"l"(v),"l"(o));
    return r;
}

// smem float offsets
#define O_WHH 0        // [256 k][96]  (gate r/z/n)*32+jj
#define O_WOT 24576    // [256 k][32]  W_out^T
#define O_WIH 32768    // [64 kk][96]  x-weights (kk<32 obs, kk>=32 y)
#define O_SH  38912    // [16 b][256 k]
#define O_P   43008    // [4 ksh][64 pos][17 u64] partials (acc*4+bm)
#define O_OBS 51712    // [16 b][32]
#define O_Y   52224    // [16 b][32]
#define O_CZ  52736    // [3 g][16 b][32 jj]
#define O_BHN 54272    // [32]
#define O_BO  54304    // [32]
#define SMF   54336
#define SMB   (SMF*4)

__global__ void __launch_bounds__(512,1) rnn_kernel(
    const float* __restrict__ init_y, const float* __restrict__ obs_seq,
    const float* __restrict__ z_dyn,  const float* __restrict__ W_ih,
    const float* __restrict__ W_hh,   const float* __restrict__ b_ih,
    const float* __restrict__ b_hh,   const float* __restrict__ W_out,
    const float* __restrict__ b_out,  float* __restrict__ out)
{
    extern __shared__ float s[];
    const int tid=threadIdx.x;
    // P1 mapping: lane = jp(4b) + kp(1b); warp = bq(2b) + ksh(2b)
    const int jp=tid&15, kp=(tid>>4)&1, bq=(tid>>5)&3, ksh=tid>>7;
    const int kbase=ksh*64+kp*32;
    // P3/P4/P5 mapping: one (batch, feature) per thread
    const int jj=tid&31, b=tid>>5;
    const int fg=blockIdx.x&7, bg=blockIdx.x>>3;

    // ---------------- prologue ----------------
    for(int e=tid;e<24576;e+=512){ int c=e>>8,k=e&255; int g=c>>5,jl=c&31;
        s[O_WHH+k*96+c]=W_hh[(g*256+fg*32+jl)*256+k]; }
    for(int e=tid;e<8192;e+=512){ int o=e>>8,k=e&255; s[O_WOT+k*32+o]=W_out[o*256+k]; }
    for(int e=tid;e<6144;e+=512){ int c=e>>6,col=e&63; int g=c>>5,jl=c&31;
        s[O_WIH+col*96+c]=W_ih[(g*256+fg*32+jl)*96+col]; }
    for(int e=tid;e<1536;e+=512){ int g=e>>9,rem=e&511; int bb=rem>>5,jl=rem&31;
        int row=g*256+fg*32+jl;
        float acc=b_ih[row]+(g<2?b_hh[row]:0.f);
        const float* zp=z_dyn+(size_t)(bg*16+bb)*32;
        #pragma unroll 8
        for(int o=0;o<32;o++) acc=fmaf(W_ih[row*96+64+o],zp[o],acc);
        s[O_CZ+e]=acc; }
    { int bb=tid>>5,kk=tid&31;
        s[O_OBS+tid]=obs_seq[((size_t)(bg*16+bb)*TT)*32+kk];
        s[O_Y+tid]=init_y[(bg*16+bb)*32+kk]; }
    for(int e=tid;e<4096;e+=512) s[O_SH+e]=0.f;
    if(tid<32){ s[O_BHN+tid]=b_hh[512+fg*32+tid]; s[O_BO+tid]=b_out[tid]; }
    __syncthreads();

    const int pos=(jj>>1)*4+(b>>2), hf=jj&1, bm=b&3;

    // ---------------- time loop ----------------
    for(int t=0;t<TT;t++){
        if(t>0){
            const int cur=t&1;
            const float4* gp=(const float4*)&g_h[cur][bg*16][0];
            float4* s4=(float4*)(s+O_SH);
            s4[tid]=__ldcg(gp+tid);
            s4[tid+512]=__ldcg(gp+tid+512);
            { int bb=tid>>5,kk=tid&31;
              s[O_OBS+tid]=obs_seq[((size_t)(bg*16+bb)*TT+t)*32+kk]; }
            __syncthreads();
        }

        // ---- P1: h-loop (R,Z,N,Y), 4-batch blocking, intra-warp k-split ----
        u64 A[16];
        #pragma unroll
        for(int i=0;i<16;i++) A[i]=0ull;
        {
            const float* wk=s+O_WHH+kbase*96+2*jp;
            const float* wy=s+O_WOT+kbase*32+2*jp;
            const float* hb=s+O_SH+(bq*4)*256+kbase;
            #pragma unroll 4
            for(int kk=0;kk<32;kk++){
                u64 wR=*(const u64*)(wk), wZ=*(const u64*)(wk+32);
                u64 wN=*(const u64*)(wk+64), wY=*(const u64*)(wy);
                #pragma unroll
                for(int i=0;i<4;i++){
                    u64 hd=dup2(hb[i*256+kk]);
                    fma2(A[i],wR,hd); fma2(A[4+i],wZ,hd);
                    fma2(A[8+i],wN,hd); fma2(A[12+i],wY,hd);
                }
                wk+=96; wy+=32;
            }
        }
        // collapse kp pairs, store partials
        #pragma unroll
        for(int i=0;i<16;i++) A[i]=bfly_add16(A[i]);
        {
            float* pp=s+O_P+(ksh*64+jp*4+bq)*34;
            if(kp==0){
                #pragma unroll
                for(int i=0;i<8;i++) *(u64*)(pp+2*i)=A[i];
            }else{
                #pragma unroll
                for(int i=8;i<16;i++) *(u64*)(pp+2*i)=A[i];
            }
        }
        __syncthreads();

        // ---- P3: reduce + y feedback/output ----
        float rs=0,zs=0,ns=0,ys=0;
        #pragma unroll
        for(int k4=0;k4<4;k4++){
            const float* p=s+O_P+(k4*64+pos)*34;
            rs+=p[bm*2+hf]; zs+=p[(4+bm)*2+hf];
            ns+=p[(8+bm)*2+hf]; ys+=p[(12+bm)*2+hf];
        }
        if(t>0){
            float y=ys+s[O_BO+jj];
            s[O_Y+b*32+jj]=y;
            if(fg==0) out[((size_t)(bg*16+b)*TT+(t-1))*32+jj]=y;
        }
        __syncthreads();

        // ---- P4: x-loop (obs + y feedback), scalar per (b,jj) ----
        float xr=0,xz=0,xn=0;
        {
            const float* wB=s+O_WIH+jj;
            const float* ob=s+O_OBS+b*32;
            const float* yb=s+O_Y+b*32;
            #pragma unroll 4
            for(int kk=0;kk<32;kk++){
                float xv=ob[kk];
                const float* w=wB+kk*96;
                xr=fmaf(w[0],xv,xr); xz=fmaf(w[32],xv,xz); xn=fmaf(w[64],xv,xn);
            }
            #pragma unroll 4
            for(int kk=0;kk<32;kk++){
                float yv=yb[kk];
                const float* w=wB+(32+kk)*96;
                xr=fmaf(w[0],yv,xr); xz=fmaf(w[32],yv,xz); xn=fmaf(w[64],yv,xn);
            }
        }
        // ---- P5: activations + h update ----
        {
            const int nb=(t+1)&1;
            float r=sigm(rs+xr+s[O_CZ+b*32+jj]);
            float zg=sigm(zs+xz+s[O_CZ+512+b*32+jj]);
            float n=tanhf(xn+s[O_CZ+1024+b*32+jj]+r*(ns+s[O_BHN+jj]));
            float hp=s[O_SH+b*256+fg*32+jj];
            g_h[nb][bg*16+b][fg*32+jj]=(1.f-zg)*n+zg*hp;
        }
        // ---- P6: global barrier ----
        __syncthreads();
        if(tid==0){
            unsigned tgt=(unsigned)(t+1)*NCTA, v;
            asm volatile("red.release.gpu.global.add.u32 [%0],1;"::"l"(&g_bar):"memory");
            do{ asm volatile("ld.acquire.gpu.global.u32 %0,[%1];":"=r"(v):"l"(&g_bar):"memory"); }while(v<tgt);
        }
        __syncthreads();
    }

    // ---------------- tail: y_{T-1} from h_T (buffer 0) ----------------
    {
        const float4* gp=(const float4*)&g_h[0][bg*16][0];
        float4* s4=(float4*)(s+O_SH);
        s4[tid]=__ldcg(gp+tid);
        s4[tid+512]=__ldcg(gp+tid+512);
        __syncthreads();
        if(fg==0){
            float acc=s[O_BO+jj];
            const float* hb=s+O_SH+b*256;
            #pragma unroll 8
            for(int k=0;k<256;k++) acc=fmaf(s[O_WOT+k*32+jj],hb[k],acc);
            out[((size_t)(bg*16+b)*TT+(TT-1))*32+jj]=acc;
        }
    }
}

extern "C" void kernel_launch(void* const* d_in, const int* in_sizes, int n_in,
                              void* d_out, int out_size)
{
    const float* init_y =(const float*)d_in[0];
    const float* obs_seq=(const float*)d_in[1];
    const float* z_dyn  =(const float*)d_in[2];
    const float* W_ih   =(const float*)d_in[3];
    const float* W_hh   =(const float*)d_in[4];
    const float* b_ih   =(const float*)d_in[5];
    const float* b_hh   =(const float*)d_in[6];
    const float* W_out  =(const float*)d_in[7];
    const float* b_out  =(const float*)d_in[8];
    float* out=(float*)d_out;

    cudaFuncSetAttribute(rnn_kernel, cudaFuncAttributeMaxDynamicSharedMemorySize, SMB);
    reset_kernel<<<1,32>>>();
    rnn_kernel<<<NCTA,512,SMB>>>(init_y,obs_seq,z_dyn,W_ih,W_hh,b_ih,b_hh,W_out,b_out,out);
}

// round 15
// speedup vs baseline: 1.0420x; 1.0420x over previous
#include <cuda_runtime.h>

typedef unsigned long long u64;
#define TT 1024
#define NCTA 128

__device__ float    g_h[2][256][256];
__device__ unsigned g_bar;

__global__ void reset_kernel(){ if(threadIdx.x==0) g_bar=0u; }

__device__ __forceinline__ void fma2(u64& d,u64 a,u64 b){ asm("fma.rn.f32x2 %0,%1,%2,%0;":"+l"(d):"l"(a),"l"(b)); }
__device__ __forceinline__ float pairsum(u64 v){ float a,b; asm("mov.b64 {%0,%1},%2;":"=f"(a),"=f"(b):"l"(v)); return a+b; }
__device__ __forceinline__ float sigm(float x){ return 1.f/(1.f+__expf(-x)); }

// smem float offsets
#define O_WHH  0      // [96 c][256 k] rows k-contig, pair-swizzled by c&15
#define O_WOT  24576  // [32 o][256 k] same swizzle
#define O_WIHO 32768  // [96 c][32 kk] obs weights, pair-swizzled
#define O_WIHY 35840  // [96 c][32 kk] y weights, pair-swizzled
#define O_H    38912  // [16 b][256 k]
#define O_P    43008  // [2 ks][4 g][16 b][32 j] scalar partials
#define O_OBS  47104  // [16 b][32]
#define O_Y    47616  // [16 b][32]
#define O_CZ   48128  // [3 g][16 b][32 j]
#define O_BHN  49664  // [32]
#define O_BO   49696  // [32]
#define SMF    49728
#define SMB    (SMF*4)

#define PP(ks,g,b) s[O_P+(((ks)*4+(g))*16+(b))*32+jj]

__global__ void __launch_bounds__(256,1) rnn_kernel(
    const float* __restrict__ init_y, const float* __restrict__ obs_seq,
    const float* __restrict__ z_dyn,  const float* __restrict__ W_ih,
    const float* __restrict__ W_hh,   const float* __restrict__ b_ih,
    const float* __restrict__ b_hh,   const float* __restrict__ W_out,
    const float* __restrict__ b_out,  float* __restrict__ out)
{
    extern __shared__ float s[];
    const int tid=threadIdx.x;
    // P1 mapping: lane=j (32 features), warp = bq(2b: 4-batch group) + ks(1b: k-half)
    const int j=tid&31, bq=(tid>>5)&3, ks=tid>>7;
    // P3/P4/P5 mapping: (jj, batches bh and bh+8)
    const int jj=tid&31, bh=tid>>5;
    const int fg=blockIdx.x&7, bg=blockIdx.x>>3;
    const int m=j&15;

    // ---------------- prologue ----------------
    for(int e=tid;e<24576;e+=256){ int c=e>>8,k=e&255; int g=c>>5,jl=c&31;
        s[O_WHH+c*256+2*((k>>1)^(c&15))+(k&1)]=W_hh[(g*256+fg*32+jl)*256+k]; }
    for(int e=tid;e<8192;e+=256){ int o=e>>8,k=e&255;
        s[O_WOT+o*256+2*((k>>1)^(o&15))+(k&1)]=W_out[o*256+k]; }
    for(int e=tid;e<3072;e+=256){ int c=e>>5,kk=e&31; int g=c>>5,jl=c&31;
        int row=(g*256+fg*32+jl)*96;
        int slot=c*32+2*((kk>>1)^(c&15))+(kk&1);
        s[O_WIHO+slot]=W_ih[row+kk];
        s[O_WIHY+slot]=W_ih[row+32+kk]; }
    for(int e=tid;e<1536;e+=256){ int g=e>>9,rem=e&511; int b=rem>>5,jl=rem&31;
        int row=g*256+fg*32+jl;
        float acc=b_ih[row]+(g<2?b_hh[row]:0.f);
        const float* zp=z_dyn+(size_t)(bg*16+b)*32;
        #pragma unroll 8
        for(int o=0;o<32;o++) acc=fmaf(W_ih[row*96+64+o],zp[o],acc);
        s[O_CZ+e]=acc; }
    for(int e=tid;e<512;e+=256){ int b=e>>5,kk=e&31;
        s[O_OBS+e]=obs_seq[((size_t)(bg*16+b)*TT)*32+kk];
        s[O_Y+e]=init_y[(bg*16+b)*32+kk]; }
    for(int e=tid;e<4096;e+=256) s[O_H+e]=0.f;
    if(tid<32){ s[O_BHN+tid]=b_hh[512+fg*32+tid]; s[O_BO+tid]=b_out[tid]; }
    __syncthreads();

    // ---------------- time loop ----------------
    for(int t=0;t<TT;t++){
        if(t>0){
            const int cur=t&1;
            const float4* gp=(const float4*)&g_h[cur][bg*16][0];
            float4* s4=(float4*)(s+O_H);
            #pragma unroll
            for(int i=0;i<4;i++) s4[tid+i*256]=__ldcg(gp+tid+i*256);
            #pragma unroll
            for(int i=0;i<2;i++){ int e=tid+i*256; int b=e>>5,kk=e&31;
                s[O_OBS+e]=obs_seq[((size_t)(bg*16+b)*TT+t)*32+kk]; }
            __syncthreads();
        }

        // ---- P1: h-loop, k-pair f32x2, XOR-swizzled weights, 4-batch blocking ----
        u64 A[16];
        #pragma unroll
        for(int i=0;i<16;i++) A[i]=0ull;
        {
            const float* wr=s+O_WHH+j*256+ks*128;
            const float* wy=s+O_WOT+j*256+ks*128;
            const float* hb=s+O_H+(bq*4)*256+ks*128;
            #pragma unroll 8
            for(int p=0;p<64;p++){
                const int px=2*(p^m);
                u64 wR=*(const u64*)(wr+px);
                u64 wZ=*(const u64*)(wr+8192+px);
                u64 wN=*(const u64*)(wr+16384+px);
                u64 wY=*(const u64*)(wy+px);
                #pragma unroll
                for(int i=0;i<4;i++){
                    u64 h2=*(const u64*)(hb+i*256+2*p);
                    fma2(A[i],wR,h2); fma2(A[4+i],wZ,h2);
                    fma2(A[8+i],wN,h2); fma2(A[12+i],wY,h2);
                }
            }
        }
        // ---- P2: pair-sum, store scalar partials ----
        #pragma unroll
        for(int g=0;g<4;g++)
            #pragma unroll
            for(int i=0;i<4;i++)
                s[O_P+((ks*4+g)*16+bq*4+i)*32+j]=pairsum(A[g*4+i]);
        __syncthreads();

        // ---- P3: reduce + y feedback/output ----
        float rs0=PP(0,0,bh)+PP(1,0,bh), zs0=PP(0,1,bh)+PP(1,1,bh), ns0=PP(0,2,bh)+PP(1,2,bh);
        float rs1=PP(0,0,bh+8)+PP(1,0,bh+8), zs1=PP(0,1,bh+8)+PP(1,1,bh+8), ns1=PP(0,2,bh+8)+PP(1,2,bh+8);
        if(t>0){
            float y0=PP(0,3,bh)+PP(1,3,bh)+s[O_BO+jj];
            float y1=PP(0,3,bh+8)+PP(1,3,bh+8)+s[O_BO+jj];
            s[O_Y+bh*32+jj]=y0; s[O_Y+(bh+8)*32+jj]=y1;
            if(fg==0){
                out[((size_t)(bg*16+bh  )*TT+(t-1))*32+jj]=y0;
                out[((size_t)(bg*16+bh+8)*TT+(t-1))*32+jj]=y1;
            }
        }
        __syncthreads();

        // ---- P4: x-loop (obs + y), k-pair packed ----
        float xr[2],xz[2],xn[2];
        #pragma unroll
        for(int u=0;u<2;u++){
            const int b=bh+8*u;
            u64 aR=0,aZ=0,aN=0;
            const float* wo=s+O_WIHO+jj*32;
            const float* wv=s+O_WIHY+jj*32;
            const float* ob=s+O_OBS+b*32;
            const float* yb=s+O_Y+b*32;
            #pragma unroll 4
            for(int p=0;p<16;p++){
                const int px=2*(p^m);
                u64 x2=*(const u64*)(ob+2*p);
                fma2(aR,*(const u64*)(wo+px     ),x2);
                fma2(aZ,*(const u64*)(wo+1024+px),x2);
                fma2(aN,*(const u64*)(wo+2048+px),x2);
                u64 y2=*(const u64*)(yb+2*p);
                fma2(aR,*(const u64*)(wv+px     ),y2);
                fma2(aZ,*(const u64*)(wv+1024+px),y2);
                fma2(aN,*(const u64*)(wv+2048+px),y2);
            }
            xr[u]=pairsum(aR); xz[u]=pairsum(aZ); xn[u]=pairsum(aN);
        }
        // ---- P5: activations + h update ----
        {
            const int nb=(t+1)&1;
            #pragma unroll
            for(int u=0;u<2;u++){
                const int b=bh+8*u;
                float rs=u?rs1:rs0, zs=u?zs1:zs0, ns=u?ns1:ns0;
                float r=sigm(rs+xr[u]+s[O_CZ+b*32+jj]);
                float zg=sigm(zs+xz[u]+s[O_CZ+512+b*32+jj]);
                float n=tanhf(xn[u]+s[O_CZ+1024+b*32+jj]+r*(ns+s[O_BHN+jj]));
                float hp=s[O_H+b*256+fg*32+jj];
                g_h[nb][bg*16+b][fg*32+jj]=(1.f-zg)*n+zg*hp;
            }
        }
        // ---- P6: global barrier ----
        __syncthreads();
        if(tid==0){
            unsigned tgt=(unsigned)(t+1)*NCTA, v;
            asm volatile("red.release.gpu.global.add.u32 [%0],1;"::"l"(&g_bar):"memory");
            do{ asm volatile("ld.acquire.gpu.global.u32 %0,[%1];":"=r"(v):"l"(&g_bar):"memory"); }while(v<tgt);
        }
        __syncthreads();
    }

    // ---------------- tail: y_{T-1} from h_T (buffer 0) ----------------
    {
        const float4* gp=(const float4*)&g_h[0][bg*16][0];
        float4* s4=(float4*)(s+O_H);
        #pragma unroll
        for(int i=0;i<4;i++) s4[tid+i*256]=__ldcg(gp+tid+i*256);
        __syncthreads();
        if(fg==0){
            #pragma unroll
            for(int u=0;u<2;u++){
                const int b=bh+8*u;
                u64 aY=0;
                const float* wy=s+O_WOT+jj*256;
                const float* hb=s+O_H+b*256;
                #pragma unroll 8
                for(int p=0;p<128;p++)
                    fma2(aY,*(const u64*)(wy+2*(p^m)),*(const u64*)(hb+2*p));
                out[((size_t)(bg*16+b)*TT+(TT-1))*32+jj]=pairsum(aY)+s[O_BO+jj];
            }
        }
    }
}

extern "C" void kernel_launch(void* const* d_in, const int* in_sizes, int n_in,
                              void* d_out, int out_size)
{
    const float* init_y =(const float*)d_in[0];
    const float* obs_seq=(const float*)d_in[1];
    const float* z_dyn  =(const float*)d_in[2];
    const float* W_ih   =(const float*)d_in[3];
    const float* W_hh   =(const float*)d_in[4];
    const float* b_ih   =(const float*)d_in[5];
    const float* b_hh   =(const float*)d_in[6];
    const float* W_out  =(const float*)d_in[7];
    const float* b_out  =(const float*)d_in[8];
    float* out=(float*)d_out;

    cudaFuncSetAttribute(rnn_kernel, cudaFuncAttributeMaxDynamicSharedMemorySize, SMB);
    reset_kernel<<<1,32>>>();
    rnn_kernel<<<NCTA,256,SMB>>>(init_y,obs_seq,z_dyn,W_ih,W_hh,b_ih,b_hh,W_out,b_out,out);
}

// round 17
// speedup vs baseline: 1.1977x; 1.1493x over previous
#include <cuda_runtime.h>

typedef unsigned long long u64;
#define TT 1024
#define NCTA 128

__device__ float    g_h[2][256][256];
__device__ unsigned g_barv[16][32];   // one counter per bg, 128B apart

__global__ void reset_kernel(){ if(threadIdx.x<16) g_barv[threadIdx.x][0]=0u; }

__device__ __forceinline__ u64 dup2(float a){ u64 r; asm("mov.b64 %0,{%1,%1};":"=l"(r):"f"(a)); return r; }
__device__ __forceinline__ void fma2(u64& d, u64 a, u64 b){ asm("fma.rn.f32x2 %0,%1,%2,%0;":"+l"(d):"l"(a),"l"(b)); }
__device__ __forceinline__ float lo2(u64 v){ float a,b; asm("mov.b64 {%0,%1},%2;":"=f"(a),"=f"(b):"l"(v)); return a; }
__device__ __forceinline__ float hi2(u64 v){ float a,b; asm("mov.b64 {%0,%1},%2;":"=f"(a),"=f"(b):"l"(v)); return b; }
__device__ __forceinline__ float sigm(float x){ return 1.f/(1.f+__expf(-x)); }

// smem float offsets
#define O_WHH 0        // [256 k][98]  cols 0..95 = (gate r/z/n)*32+jj, pad 2
#define O_WOT 25088    // [256 k][34]  W_out^T cols 0..31, pad 2
#define O_WIH 33792    // [64 kk][96]  x-weights (kk<32 obs, kk>=32 y)
#define O_SH  39936    // [16 b][260]  h staged (stride 260: 16B-aligned, bank-staggered)
#define O_P   44096    // [4 ks][64 pos][17 u64] partials
#define O_OBS2 52800   // u64[32 kk][9] packed (b, b+8)
#define O_Y2  53376    // u64[32 o][9]  packed (b, b+8)
#define O_CZ  53952    // [3 g][16 b][32 jj]
#define O_BHN 55488    // [32]
#define O_BO  55520    // [32]
#define SMF   55552
#define SMB   (SMF*4)

__global__ void __launch_bounds__(256,1) rnn_kernel(
    const float* __restrict__ init_y, const float* __restrict__ obs_seq,
    const float* __restrict__ z_dyn,  const float* __restrict__ W_ih,
    const float* __restrict__ W_hh,   const float* __restrict__ b_ih,
    const float* __restrict__ b_hh,   const float* __restrict__ W_out,
    const float* __restrict__ b_out,  float* __restrict__ out)
{
    extern __shared__ float s[];
    const int tid=threadIdx.x;
    // P1 mapping
    const int jp=tid&15, bq=(tid>>4)&3, ks=tid>>6;
    // P3/P4/P5 mapping
    const int jj=tid&31, bh=tid>>5;              // batches bh and bh+8
    const int fg=blockIdx.x&7, bg=blockIdx.x>>3;
    // warp-local staging mapping
    const int w=tid>>5, l=tid&31;
    const int B0=(w&1)*8, bloc=l>>2, kq=w>>1;    // warp stages b=B0..B0+7, k=kq*64..+63

    // ---------------- prologue ----------------
    for(int e=tid;e<24576;e+=256){ int c=e>>8,k=e&255; int g=c>>5,jl=c&31;
        s[O_WHH+k*98+c]=W_hh[(g*256+fg*32+jl)*256+k]; }
    for(int e=tid;e<8192;e+=256){ int o=e>>8,k=e&255; s[O_WOT+k*34+o]=W_out[o*256+k]; }
    for(int e=tid;e<6144;e+=256){ int c=e>>6,col=e&63; int g=c>>5,jl=c&31;
        s[O_WIH+col*96+c]=W_ih[(g*256+fg*32+jl)*96+col]; }
    for(int e=tid;e<1536;e+=256){ int g=e>>9,rem=e&511; int b=rem>>5,jl=rem&31;
        int row=g*256+fg*32+jl;
        float acc=b_ih[row]+(g<2?b_hh[row]:0.f);
        const float* zp=z_dyn+(size_t)(bg*16+b)*32;
        #pragma unroll 8
        for(int o=0;o<32;o++) acc=fmaf(W_ih[row*96+64+o],zp[o],acc);
        s[O_CZ+e]=acc; }
    for(int e=tid;e<512;e+=256){ int b=e>>5,kk=e&31;
        s[O_OBS2+(kk*9+(b&7))*2+(b>>3)]=obs_seq[((size_t)(bg*16+b)*TT)*32+kk];
        s[O_Y2  +(kk*9+(b&7))*2+(b>>3)]=init_y[(bg*16+b)*32+kk]; }
    for(int e=tid;e<4160;e+=256) s[O_SH+e]=0.f;
    if(tid<32){ s[O_BHN+tid]=b_hh[512+fg*32+tid]; s[O_BO+tid]=b_out[tid]; }
    __syncthreads();

    const int pos0=(jj>>1)+16*(bh>>2), pos1=pos0+32, hf=jj&1, bm=(bh&3);
    volatile unsigned* barp=&g_barv[bg][0];

    // ---------------- time loop ----------------
    for(int t=0;t<TT;t++){
        if(t>0){
            // warp-local h staging: this warp's 8 batches x 64 k
            const int cur=t&1;
            const float4* gp=(const float4*)&g_h[cur][bg*16][0];
            #pragma unroll
            for(int i=0;i<4;i++){
                int k4=(l&3)+4*i;
                float4 v=__ldcg(gp+((B0+bloc)*256+kq*64)/4+k4);
                *(float4*)(s+O_SH+(B0+bloc)*260+kq*64+4*k4)=v;
            }
            __syncwarp();
            // obs staging (consumed in P4, after P2/P3 syncs)
            #pragma unroll
            for(int i=0;i<2;i++){ int e=tid+i*256; int b=e>>5,kk=e&31;
                s[O_OBS2+(kk*9+(b&7))*2+(b>>3)]=obs_seq[((size_t)(bg*16+b)*TT+t)*32+kk]; }
        }

        // ---- P1: h-loop, 4-batch register blocking, gates R,Z,HN,Y ----
        u64 A[16];
        #pragma unroll
        for(int i=0;i<16;i++) A[i]=0ull;
        {
            const float* wk=s+O_WHH+(ks*64)*98+2*jp;
            const float* wy=s+O_WOT+(ks*64)*34+2*jp;
            const float* hb=s+O_SH+(bq*4)*260+ks*64;
            #pragma unroll 4
            for(int kk=0;kk<64;kk++){
                u64 wR=*(const u64*)(wk), wZ=*(const u64*)(wk+32);
                u64 wN=*(const u64*)(wk+64), wY=*(const u64*)(wy);
                #pragma unroll
                for(int i=0;i<4;i++){
                    u64 hd=dup2(hb[i*260+kk]);
                    fma2(A[i],wR,hd); fma2(A[4+i],wZ,hd);
                    fma2(A[8+i],wN,hd); fma2(A[12+i],wY,hd);
                }
                wk+=98; wy+=34;
            }
        }
        // ---- P2: store partials ----
        {
            float* pp=s+O_P+ks*2176+(jp+16*bq)*34;
            #pragma unroll
            for(int i=0;i<16;i++) *(u64*)(pp+2*i)=A[i];
        }
        __syncthreads();

        // ---- P3: reduce gates + y feedback/output ----
        float rs0=0,zs0=0,ns0=0,rs1=0,zs1=0,ns1=0;
        {
            #pragma unroll
            for(int k4=0;k4<4;k4++){
                const float* p0=s+O_P+k4*2176+pos0*34+hf;
                const float* p1=s+O_P+k4*2176+pos1*34+hf;
                rs0+=p0[bm*2]; zs0+=p0[(4+bm)*2]; ns0+=p0[(8+bm)*2];
                rs1+=p1[bm*2]; zs1+=p1[(4+bm)*2]; ns1+=p1[(8+bm)*2];
            }
            if(t>0){
                float y0=s[O_BO+jj], y1=y0;
                #pragma unroll
                for(int k4=0;k4<4;k4++){
                    y0+=s[O_P+k4*2176+pos0*34+(12+bm)*2+hf];
                    y1+=s[O_P+k4*2176+pos1*34+(12+bm)*2+hf];
                }
                u64 yp; asm("mov.b64 %0,{%1,%2};":"=l"(yp):"f"(y0),"f"(y1));
                *(u64*)(s+O_Y2+(jj*9+bh)*2)=yp;
                if(fg==0){
                    out[((size_t)(bg*16+bh  )*TT+(t-1))*32+jj]=y0;
                    out[((size_t)(bg*16+bh+8)*TT+(t-1))*32+jj]=y1;
                }
            }
        }
        __syncthreads();

        // ---- P4: x-loop (obs + y feedback), batches packed in f32x2 ----
        u64 XR=0,XZ=0,XN=0;
        {
            const float* wx=s+O_WIH+jj;
            const u64* xo=(const u64*)(s+O_OBS2)+bh;
            const u64* xy=(const u64*)(s+O_Y2)+bh;
            #pragma unroll 4
            for(int kk=0;kk<32;kk++){
                u64 x2=xo[kk*9];
                const float* ww=wx+kk*96;
                fma2(XR,dup2(ww[0]),x2); fma2(XZ,dup2(ww[32]),x2); fma2(XN,dup2(ww[64]),x2);
            }
            #pragma unroll 4
            for(int kk=0;kk<32;kk++){
                u64 y2=xy[kk*9];
                const float* ww=wx+(32+kk)*96;
                fma2(XR,dup2(ww[0]),y2); fma2(XZ,dup2(ww[32]),y2); fma2(XN,dup2(ww[64]),y2);
            }
        }
        // ---- P5: activations + h update ----
        {
            const int nb=(t+1)&1;
            float r0=sigm(rs0+lo2(XR)+s[O_CZ+bh*32+jj]);
            float z0=sigm(zs0+lo2(XZ)+s[O_CZ+512+bh*32+jj]);
            float n0=tanhf(lo2(XN)+s[O_CZ+1024+bh*32+jj]+r0*(ns0+s[O_BHN+jj]));
            float hp0=s[O_SH+bh*260+fg*32+jj];
            g_h[nb][bg*16+bh][fg*32+jj]=(1.f-z0)*n0+z0*hp0;
            float r1=sigm(rs1+hi2(XR)+s[O_CZ+(bh+8)*32+jj]);
            float z1=sigm(zs1+hi2(XZ)+s[O_CZ+512+(bh+8)*32+jj]);
            float n1=tanhf(hi2(XN)+s[O_CZ+1024+(bh+8)*32+jj]+r1*(ns1+s[O_BHN+jj]));
            float hp1=s[O_SH+(bh+8)*260+fg*32+jj];
            g_h[nb][bg*16+bh+8][fg*32+jj]=(1.f-z1)*n1+z1*hp1;
        }
        // ---- P6: group-of-8 barrier ----
        __syncthreads();
        if(tid==0){
            unsigned tgt=(unsigned)(t+1)*8u, v;
            asm volatile("red.release.gpu.global.add.u32 [%0],1;"::"l"((unsigned*)barp):"memory");
            do{ asm volatile("ld.acquire.gpu.global.u32 %0,[%1];":"=r"(v):"l"((unsigned*)barp):"memory"); }while(v<tgt);
        }
        __syncthreads();
    }

    // ---------------- tail: y_{T-1} from h_T (buffer 0), fg==0 only ----------------
    if(fg==0){
        for(int e=tid;e<1024;e+=256){ int b=e>>6,k4=e&63;
            *(float4*)(s+O_SH+b*260+4*k4)=__ldcg((const float4*)&g_h[0][bg*16+b][0]+k4); }
        __syncthreads();
        const float* hb=s+O_SH+bh*260;
        const float* hb1=s+O_SH+(bh+8)*260;
        float y0=s[O_BO+jj], y1=y0;
        #pragma unroll 8
        for(int k=0;k<256;k++){
            float wv=s[O_WOT+k*34+jj];
            y0=fmaf(wv,hb[k],y0); y1=fmaf(wv,hb1[k],y1);
        }
        out[((size_t)(bg*16+bh  )*TT+(TT-1))*32+jj]=y0;
        out[((size_t)(bg*16+bh+8)*TT+(TT-1))*32+jj]=y1;
    }
}

extern "C" void kernel_launch(void* const* d_in, const int* in_sizes, int n_in,
                              void* d_out, int out_size)
{
    const float* init_y =(const float*)d_in[0];
    const float* obs_seq=(const float*)d_in[1];
    const float* z_dyn  =(const float*)d_in[2];
    const float* W_ih   =(const float*)d_in[3];
    const float* W_hh   =(const float*)d_in[4];
    const float* b_ih   =(const float*)d_in[5];
    const float* b_hh   =(const float*)d_in[6];
    const float* W_out  =(const float*)d_in[7];
    const float* b_out  =(const float*)d_in[8];
    float* out=(float*)d_out;

    cudaFuncSetAttribute(rnn_kernel, cudaFuncAttributeMaxDynamicSharedMemorySize, SMB);
    reset_kernel<<<1,32>>>();
    rnn_kernel<<<NCTA,256,SMB>>>(init_y,obs_seq,z_dyn,W_ih,W_hh,b_ih,b_hh,W_out,b_out,out);
}